// round 1
// baseline (speedup 1.0000x reference)
#include <cuda_runtime.h>
#include <math_constants.h>

#define BATCH 256
#define NA 196
#define NB 196
#define DK 256
#define DIM 1024
#define SMOOTH_F 4.0f

// Scratch for attention weights (39.3 MB) — device global, no allocation.
__device__ float g_attn[(size_t)BATCH * NA * NB];

typedef unsigned long long u64;

__device__ __forceinline__ u64 pack2(float x, float y) {
    u64 r;
    asm("mov.b64 %0, {%1, %2};" : "=l"(r) : "r"(__float_as_uint(x)), "r"(__float_as_uint(y)));
    return r;
}
__device__ __forceinline__ void unpack2(u64 v, float& x, float& y) {
    unsigned lo, hi;
    asm("mov.b64 {%0, %1}, %2;" : "=r"(lo), "=r"(hi) : "l"(v));
    x = __uint_as_float(lo);
    y = __uint_as_float(hi);
}
// Packed fp32x2 FMA (Blackwell): d = a*b + d, lane-wise, exact fp32 semantics.
__device__ __forceinline__ u64 fma2(u64 a, u64 b, u64 c) {
    asm("fma.rn.f32x2 %0, %1, %2, %0;" : "+l"(c) : "l"(a), "l"(b));
    return c;
}

// ============================================================================
// Kernel 1: energy = Q_a @ K_b, softmax(energy*SMOOTH) -> g_attn
// One block per batch. key_b[b] (256x196 fp32 = 196KB) resident in SMEM.
// Processes 4 query rows per pass (f32x2 pairs over rows).
// ============================================================================
__global__ void __launch_bounds__(256) xattn_k1(
    const float* __restrict__ query_a,   // [B, NA, DK]
    const float* __restrict__ key_b)     // [B, DK, NB]
{
    extern __shared__ float sm[];
    float* key_s = sm;                    // DK*NB = 50176 floats
    float* q_s   = sm + DK * NB;          // [DK][4] = 1024 floats
    float* redm  = q_s + DK * 4;          // 32 floats
    float* reds  = redm + 32;             // 32 floats

    const int b = blockIdx.x;
    const int t = threadIdx.x;
    const int lane = t & 31;
    const int wid  = t >> 5;
    const bool act = (t < NB);

    // Load key_b[b] into SMEM, coalesced float4.
    {
        const float4* src = (const float4*)(key_b + (size_t)b * DK * NB);
        float4* dst = (float4*)key_s;
        #pragma unroll
        for (int i = 0; i < (DK * NB / 4) / 256; i++)
            dst[t + i * 256] = src[t + i * 256];
    }

    const float* qb = query_a + (size_t)b * NA * DK;

    for (int ab = 0; ab < NA / 4; ab++) {
        const int a0 = ab * 4;
        __syncthreads();   // S1: previous iteration done with q_s / reds
        // Load 4 query rows, transposed to [k][row] for paired access.
        #pragma unroll
        for (int j = 0; j < 4; j++)
            q_s[t * 4 + j] = qb[(size_t)(a0 + j) * DK + t];
        __syncthreads();   // S2

        u64 acc01 = 0ull, acc23 = 0ull;  // (0.0f, 0.0f) bit pattern
        if (act) {
            const ulonglong2* q2 = (const ulonglong2*)q_s;
            #pragma unroll 8
            for (int k = 0; k < DK; k++) {
                float kv = key_s[k * NB + t];
                u64 kd = pack2(kv, kv);
                ulonglong2 qq = q2[k];
                acc01 = fma2(kd, qq.x, acc01);
                acc23 = fma2(kd, qq.y, acc23);
            }
        }
        float e[4];
        unpack2(acc01, e[0], e[1]);
        unpack2(acc23, e[2], e[3]);

        // Row max (block-wide over 196 active threads)
        #pragma unroll
        for (int r = 0; r < 4; r++) {
            float v = act ? e[r] : -CUDART_INF_F;
            #pragma unroll
            for (int o = 16; o; o >>= 1)
                v = fmaxf(v, __shfl_xor_sync(0xFFFFFFFFu, v, o));
            if (lane == 0) redm[r * 8 + wid] = v;
        }
        __syncthreads();   // S3

        float p[4];
        #pragma unroll
        for (int r = 0; r < 4; r++) {
            float m = redm[r * 8];
            #pragma unroll
            for (int w = 1; w < 8; w++) m = fmaxf(m, redm[r * 8 + w]);
            p[r] = act ? __expf(SMOOTH_F * (e[r] - m)) : 0.0f;
            float s = p[r];
            #pragma unroll
            for (int o = 16; o; o >>= 1)
                s += __shfl_xor_sync(0xFFFFFFFFu, s, o);
            if (lane == 0) reds[r * 8 + wid] = s;
        }
        __syncthreads();   // S4

        #pragma unroll
        for (int r = 0; r < 4; r++) {
            float s = 0.0f;
            #pragma unroll
            for (int w = 0; w < 8; w++) s += reds[r * 8 + w];
            float inv = 1.0f / s;
            if (act)
                g_attn[((size_t)b * NA + a0 + r) * NB + t] = p[r] * inv;
        }
    }
}

// ============================================================================
// Kernel 2: out = gamma + V_a @ attn + V_b
// Per batch: [DIM x NA] @ [NA x NB]. Block tile 128(M=dim) x 64(N), K-chunk 28.
// Per-thread 8Mx4N register tile as f32x2 pairs along M -> 16 FFMA2 per k.
// ============================================================================
#define TM 128
#define TN 64
#define KCH 28

__global__ void __launch_bounds__(256) xattn_k2(
    const float* __restrict__ value_a,   // [B, DIM, NA]
    const float* __restrict__ value_b,   // [B, DIM, NB]
    const float* __restrict__ gamma,     // [1]
    float* __restrict__ out)             // [B, DIM, NB]
{
    __shared__ float va_s[KCH][TM + 4];  // +4 pad: keeps 16B alignment, cuts STS conflicts
    __shared__ float at_s[KCH][TN];

    const int b  = blockIdx.z;
    const int m0 = blockIdx.y * TM;
    const int n0 = blockIdx.x * TN;
    const int t  = threadIdx.x;
    const int tm = t >> 4;   // 0..15 -> M offset tm*8
    const int tn = t & 15;   // 0..15 -> N offset tn*4

    u64 acc[4][4];
    #pragma unroll
    for (int i = 0; i < 4; i++)
        #pragma unroll
        for (int j = 0; j < 4; j++) acc[i][j] = 0ull;

    const float g = gamma[0];
    const float* vab = value_a + (size_t)b * DIM * NA;
    const float* atb = g_attn + (size_t)b * NA * NB;

    #pragma unroll 1
    for (int k0 = 0; k0 < NA; k0 += KCH) {
        __syncthreads();
        // Load V_a tile [TM rows x KCH] -> SMEM transposed [KCH][TM].
        // Coalesced-ish gmem reads (28 contiguous floats per row).
        #pragma unroll
        for (int i = 0; i < (TM * KCH) / 256; i++) {   // 14
            int idx = t + i * 256;
            int al = idx % KCH;
            int dl = idx / KCH;
            va_s[al][dl] = vab[(size_t)(m0 + dl) * NA + (k0 + al)];
        }
        // Load attn tile [KCH][TN], zero-pad n >= NB.
        #pragma unroll
        for (int i = 0; i < (KCH * TN) / 256; i++) {   // 7
            int idx = t + i * 256;
            int nl = idx & 63;
            int kl = idx >> 6;
            int n = n0 + nl;
            at_s[kl][nl] = (n < NB) ? atb[(size_t)(k0 + kl) * NB + n] : 0.0f;
        }
        __syncthreads();

        #pragma unroll
        for (int kk = 0; kk < KCH; kk++) {
            const ulonglong2* ap = (const ulonglong2*)&va_s[kk][tm * 8];
            ulonglong2 a01 = ap[0];
            ulonglong2 a23 = ap[1];
            float4 bv = *(const float4*)&at_s[kk][tn * 4];
            u64 av[4] = { a01.x, a01.y, a23.x, a23.y };
            u64 bd[4] = { pack2(bv.x, bv.x), pack2(bv.y, bv.y),
                          pack2(bv.z, bv.z), pack2(bv.w, bv.w) };
            #pragma unroll
            for (int i = 0; i < 4; i++)
                #pragma unroll
                for (int j = 0; j < 4; j++)
                    acc[i][j] = fma2(av[i], bd[j], acc[i][j]);
        }
    }

    // Epilogue: out = gamma + acc + value_b  (NB % 4 == 0 -> float4 always legal)
    const int n = n0 + tn * 4;
    if (n < NB) {
        #pragma unroll
        for (int i = 0; i < 4; i++) {
            #pragma unroll
            for (int h = 0; h < 2; h++) {
                int m = m0 + tm * 8 + i * 2 + h;
                float r[4];
                #pragma unroll
                for (int j = 0; j < 4; j++) {
                    float lo, hi;
                    unpack2(acc[i][j], lo, hi);
                    r[j] = h ? hi : lo;
                }
                size_t base = ((size_t)b * DIM + m) * NB + n;
                float4 v = *(const float4*)(value_b + base);
                float4 o;
                o.x = g + r[0] + v.x;
                o.y = g + r[1] + v.y;
                o.z = g + r[2] + v.z;
                o.w = g + r[3] + v.w;
                *(float4*)(out + base) = o;
            }
        }
    }
}

// ============================================================================
extern "C" void kernel_launch(void* const* d_in, const int* in_sizes, int n_in,
                              void* d_out, int out_size)
{
    const float* query_a = (const float*)d_in[0];
    const float* value_a = (const float*)d_in[1];
    const float* key_b   = (const float*)d_in[2];
    const float* value_b = (const float*)d_in[3];
    const float* gamma   = (const float*)d_in[4];
    float* out = (float*)d_out;

    const int smem1 = (DK * NB + DK * 4 + 64) * (int)sizeof(float);  // 205056 B
    cudaFuncSetAttribute(xattn_k1, cudaFuncAttributeMaxDynamicSharedMemorySize, smem1);

    xattn_k1<<<BATCH, 256, smem1>>>(query_a, key_b);

    dim3 g2((NB + TN - 1) / TN, DIM / TM, BATCH);  // (4, 8, 256)
    xattn_k2<<<g2, 256>>>(value_a, value_b, gamma, out);
}

// round 7
// speedup vs baseline: 2.1976x; 2.1976x over previous
#include <cuda_runtime.h>
#include <cuda_bf16.h>
#include <cstdint>

#define BATCH 256
#define NA 196
#define NB 196
#define DK 256
#define DIM 1024
#define SMOOTH_F 4.0f
#define NP 224   // padded n / a dims

// Pre-split attention planes: attnT[b][n][a], bf16 high & low parts, zero-padded.
__device__ unsigned short g_ah[(size_t)BATCH * NP * NP];
__device__ unsigned short g_al[(size_t)BATCH * NP * NP];

typedef unsigned int u32;

__device__ __forceinline__ u32 smem_u32(const void* p) {
    u32 a;
    asm("{ .reg .u64 t; cvta.to.shared.u64 t, %1; cvt.u32.u64 %0, t; }" : "=r"(a) : "l"(p));
    return a;
}
__device__ __forceinline__ void split2(float x, unsigned short& h, unsigned short& l) {
    __nv_bfloat16 hb = __float2bfloat16_rn(x);
    float r = x - __bfloat162float(hb);
    h = __bfloat16_as_ushort(hb);
    l = __bfloat16_as_ushort(__float2bfloat16_rn(r));
}

#define LDMX4(r, a) asm volatile( \
    "ldmatrix.sync.aligned.m8n8.x4.shared.b16 {%0,%1,%2,%3}, [%4];" \
    : "=r"((r)[0]), "=r"((r)[1]), "=r"((r)[2]), "=r"((r)[3]) : "r"(a))

#define MMA16816(d, a, b0, b1) asm volatile( \
    "mma.sync.aligned.m16n8k16.row.col.f32.bf16.bf16.f32 " \
    "{%0,%1,%2,%3}, {%4,%5,%6,%7}, {%8,%9}, {%0,%1,%2,%3};" \
    : "+f"((d)[0]), "+f"((d)[1]), "+f"((d)[2]), "+f"((d)[3]) \
    : "r"((a)[0]), "r"((a)[1]), "r"((a)[2]), "r"((a)[3]), "r"(b0), "r"(b1))

#define CPASYNC16(dst, src) asm volatile( \
    "cp.async.cg.shared.global [%0], [%1], 16;" :: "r"(dst), "l"(src))
#define CPCOMMIT() asm volatile("cp.async.commit_group;")
#define CPWAIT1() asm volatile("cp.async.wait_group 1;")

// ============================================================================
// K1: energyT[n][a] = K_b^T @ Q_a^T (2-term split, 3 MMA products),
//     column softmax, write pre-split attn planes.
// Block: (a-half, batch). 224 threads = 7 warps; warp = 32 n-rows x 112 a-cols.
// ============================================================================
#define K1_AH 0u
#define K1_AL 17920u      // A planes: [224 n][32 k] bf16, 80B row stride
#define K1_BH 35840u      // B planes: [112 a][32 k] bf16, 80B row stride
#define K1_BL 44800u
#define K1_SMEM 103936u   // also Csm overlay: [224][116] f32 = 103936 B

__global__ void __launch_bounds__(224) xattn_k1(
    const float* __restrict__ Q,    // [B, NA, DK]
    const float* __restrict__ Kb)   // [B, DK, NB]
{
    extern __shared__ char smp[];
    const u32 sb = smem_u32(smp);
    const int t = threadIdx.x, lane = t & 31, w = t >> 5;
    const int a0 = blockIdx.x * 112;
    const int b  = blockIdx.y;

    const float* qb = Q + (size_t)b * NA * DK;
    const float* kb = Kb + (size_t)b * DK * NB;

    float acc[2][14][4];
    #pragma unroll
    for (int mt = 0; mt < 2; mt++)
        #pragma unroll
        for (int j = 0; j < 14; j++)
            #pragma unroll
            for (int q = 0; q < 4; q++) acc[mt][j][q] = 0.f;

    #pragma unroll 1
    for (int kc = 0; kc < 8; kc++) {
        __syncthreads();
        // A = K^T: row n = t, cols k (32). Coalesced gmem reads along n.
        #pragma unroll
        for (int i = 0; i < 32; i++) {
            float v = (t < NB) ? kb[(size_t)(kc * 32 + i) * NB + t] : 0.f;
            unsigned short h, l;
            split2(v, h, l);
            *(unsigned short*)(smp + K1_AH + t * 80 + i * 2) = h;
            *(unsigned short*)(smp + K1_AL + t * 80 + i * 2) = l;
        }
        // B = Q rows (a-local 112) x 32 k
        #pragma unroll
        for (int i = 0; i < 16; i++) {
            int idx = t + i * 224;
            int r = idx >> 5, kk = idx & 31;
            int a = a0 + r;
            float v = (a < NA) ? qb[(size_t)a * DK + kc * 32 + kk] : 0.f;
            unsigned short h, l;
            split2(v, h, l);
            *(unsigned short*)(smp + K1_BH + r * 80 + kk * 2) = h;
            *(unsigned short*)(smp + K1_BL + r * 80 + kk * 2) = l;
        }
        __syncthreads();

        #pragma unroll
        for (int ks = 0; ks < 2; ks++) {
            u32 ah[2][4], al[2][4];
            #pragma unroll
            for (int mt = 0; mt < 2; mt++) {
                u32 arow = w * 32 + mt * 16 + (lane & 15);
                u32 acol = ks * 32 + ((lane >> 4) << 4);
                LDMX4(ah[mt], sb + K1_AH + arow * 80 + acol);
                LDMX4(al[mt], sb + K1_AL + arow * 80 + acol);
            }
            #pragma unroll
            for (int jj = 0; jj < 7; jj++) {
                u32 brow = jj * 16 + ((lane >> 4) << 3) + (lane & 7);
                u32 bcol = ks * 32 + (((lane >> 3) & 1) << 4);
                u32 bh[4], bl[4];
                LDMX4(bh, sb + K1_BH + brow * 80 + bcol);
                LDMX4(bl, sb + K1_BL + brow * 80 + bcol);
                #pragma unroll
                for (int mt = 0; mt < 2; mt++) {
                    #pragma unroll
                    for (int hf = 0; hf < 2; hf++) {
                        int j = jj * 2 + hf;
                        MMA16816(acc[mt][j], ah[mt], bh[hf * 2], bh[hf * 2 + 1]);
                        MMA16816(acc[mt][j], ah[mt], bl[hf * 2], bl[hf * 2 + 1]);
                        MMA16816(acc[mt][j], al[mt], bh[hf * 2], bh[hf * 2 + 1]);
                    }
                }
            }
        }
    }
    __syncthreads();   // staging dead; reuse as Csm [224 n][116 f32]

    float* Csm = (float*)smp;
    const int g = lane >> 2, tq = lane & 3;
    #pragma unroll
    for (int mt = 0; mt < 2; mt++)
        #pragma unroll
        for (int j = 0; j < 14; j++) {
            int row = w * 32 + mt * 16 + g;
            int col = j * 8 + tq * 2;
            *(float2*)&Csm[row * 116 + col] = make_float2(acc[mt][j][0], acc[mt][j][1]);
            *(float2*)&Csm[(row + 8) * 116 + col] = make_float2(acc[mt][j][2], acc[mt][j][3]);
        }
    __syncthreads();

    // Column softmax (axis n), thread per a-column.
    if (t < 112) {
        float M = -1e30f;
        for (int n = 0; n < NB; n++) M = fmaxf(M, Csm[n * 116 + t]);
        float S = 0.f;
        for (int n = 0; n < NB; n++) {
            float e = __expf(SMOOTH_F * (Csm[n * 116 + t] - M));
            Csm[n * 116 + t] = e;
            S += e;
        }
        float inv = (a0 + t < NA) ? (1.f / S) : 0.f;
        for (int n = 0; n < NB; n++) Csm[n * 116 + t] *= inv;
    }
    __syncthreads();

    // Write pre-split planes (coalesced rows; zero rows for n >= 196).
    for (int r = w; r < NP; r += 7) {
        if (lane < 28) {
            uint2 hh = make_uint2(0u, 0u), ll = make_uint2(0u, 0u);
            if (r < NB) {
                float4 p = *(float4*)&Csm[r * 116 + lane * 4];
                unsigned short h[4], l[4];
                split2(p.x, h[0], l[0]); split2(p.y, h[1], l[1]);
                split2(p.z, h[2], l[2]); split2(p.w, h[3], l[3]);
                hh = make_uint2((u32)h[0] | ((u32)h[1] << 16), (u32)h[2] | ((u32)h[3] << 16));
                ll = make_uint2((u32)l[0] | ((u32)l[1] << 16), (u32)l[2] | ((u32)l[3] << 16));
            }
            size_t off = (size_t)(b * NP + r) * NP + a0 + lane * 4;
            *(uint2*)(g_ah + off) = hh;
            *(uint2*)(g_al + off) = ll;
        }
    }
}

// ============================================================================
// K2: out = gamma + V_a @ attn + V_b.
// Block: (m-tile 128 dims, batch). 256 threads = 8 warps (4 M x 2 N).
// A (V_a split) resident full-K in smem; B (attn planes) cp.async double-buf.
// ============================================================================
#define K2_AH 0u
#define K2_AL 59392u                  // A planes: [128][224 k] bf16, 464B stride
#define K2_B0 118784u                 // B stages: [224 n][32 k] bf16, 80B stride
#define K2_BSTAGE 35840u              // per stage: 2 planes x 17920
#define K2_SMEM 190464u

__global__ void __launch_bounds__(256) xattn_k2(
    const float* __restrict__ VA,   // [B, DIM, NA]
    const float* __restrict__ VB,   // [B, DIM, NB]
    const float* __restrict__ G,
    float* __restrict__ O)          // [B, DIM, NB]
{
    extern __shared__ char smp[];
    const u32 sb = smem_u32(smp);
    const int t = threadIdx.x, lane = t & 31, w = t >> 5;
    const int wm = w >> 1, wn = w & 1;
    const int m0 = blockIdx.x * 128;
    const int b  = blockIdx.y;

    const float* va = VA + ((size_t)b * DIM + m0) * NA;
    const char* ghp = (const char*)g_ah;
    const char* glp = (const char*)g_al;

    // prefetch B chunk 0 into stage 0
    {
        const int kc = 0, st = 0;
        #pragma unroll
        for (int i = 0; i < 7; i++) {
            int idx = t + i * 256;
            int p = idx / 896, rem = idx % 896;
            int n = rem >> 2, c = rem & 3;
            u32 dst = sb + K2_B0 + st * K2_BSTAGE + p * 17920 + n * 80 + c * 16;
            const char* base = p ? glp : ghp;
            const char* src = base + ((size_t)(b * NP + n) * NP + kc * 32 + c * 8) * 2;
            CPASYNC16(dst, src);
        }
        CPCOMMIT();
    }

    // Fill resident A planes: V_a split, rows m (128) x k=a (224, zero-pad)
    #pragma unroll
    for (int i = 0; i < 28; i++) {
        int idx = t + i * 256;
        int row = idx / 56, q4 = idx % 56;
        int col = q4 * 4;
        float4 v = make_float4(0.f, 0.f, 0.f, 0.f);
        if (col < NA) v = *(const float4*)(va + (size_t)row * NA + col);
        unsigned short h[4], l[4];
        split2(v.x, h[0], l[0]); split2(v.y, h[1], l[1]);
        split2(v.z, h[2], l[2]); split2(v.w, h[3], l[3]);
        *(uint2*)(smp + K2_AH + row * 464 + col * 2) =
            make_uint2((u32)h[0] | ((u32)h[1] << 16), (u32)h[2] | ((u32)h[3] << 16));
        *(uint2*)(smp + K2_AL + row * 464 + col * 2) =
            make_uint2((u32)l[0] | ((u32)l[1] << 16), (u32)l[2] | ((u32)l[3] << 16));
    }

    float acc[2][14][4];
    #pragma unroll
    for (int mt = 0; mt < 2; mt++)
        #pragma unroll
        for (int j = 0; j < 14; j++)
            #pragma unroll
            for (int q = 0; q < 4; q++) acc[mt][j][q] = 0.f;

    #pragma unroll 1
    for (int kc = 0; kc < 7; kc++) {
        if (kc < 6) {   // prefetch next chunk
            const int nk = kc + 1, st = nk & 1;
            #pragma unroll
            for (int i = 0; i < 7; i++) {
                int idx = t + i * 256;
                int p = idx / 896, rem = idx % 896;
                int n = rem >> 2, c = rem & 3;
                u32 dst = sb + K2_B0 + st * K2_BSTAGE + p * 17920 + n * 80 + c * 16;
                const char* base = p ? glp : ghp;
                const char* src = base + ((size_t)(b * NP + n) * NP + nk * 32 + c * 8) * 2;
                CPASYNC16(dst, src);
            }
        }
        CPCOMMIT();
        CPWAIT1();
        __syncthreads();

        const u32 bhb = sb + K2_B0 + (kc & 1) * K2_BSTAGE;
        const u32 blb = bhb + 17920;

        #pragma unroll
        for (int ks = 0; ks < 2; ks++) {
            u32 ah[2][4], al[2][4];
            #pragma unroll
            for (int mt = 0; mt < 2; mt++) {
                u32 arow = wm * 32 + mt * 16 + (lane & 15);
                u32 acol = (kc * 2 + ks) * 32 + ((lane >> 4) << 4);
                LDMX4(ah[mt], sb + K2_AH + arow * 464 + acol);
                LDMX4(al[mt], sb + K2_AL + arow * 464 + acol);
            }
            #pragma unroll
            for (int jj = 0; jj < 7; jj++) {
                u32 brow = wn * 112 + jj * 16 + ((lane >> 4) << 3) + (lane & 7);
                u32 bcol = ks * 32 + (((lane >> 3) & 1) << 4);
                u32 bh[4], bl[4];
                LDMX4(bh, bhb + brow * 80 + bcol);
                LDMX4(bl, blb + brow * 80 + bcol);
                #pragma unroll
                for (int mt = 0; mt < 2; mt++) {
                    #pragma unroll
                    for (int hf = 0; hf < 2; hf++) {
                        int j = jj * 2 + hf;
                        MMA16816(acc[mt][j], ah[mt], bh[hf * 2], bh[hf * 2 + 1]);
                        MMA16816(acc[mt][j], ah[mt], bl[hf * 2], bl[hf * 2 + 1]);
                        MMA16816(acc[mt][j], al[mt], bh[hf * 2], bh[hf * 2 + 1]);
                    }
                }
            }
        }
        __syncthreads();
    }

    // Epilogue: out = gamma + acc + V_b (guarded float2 stores)
    const float gam = G[0];
    const int g = lane >> 2, tq = lane & 3;
    #pragma unroll
    for (int mt = 0; mt < 2; mt++)
        #pragma unroll
        for (int j = 0; j < 14; j++) {
            int n = wn * 112 + j * 8 + tq * 2;
            if (n < NB) {
                int row = m0 + wm * 32 + mt * 16 + g;
                size_t o0 = ((size_t)(b * DIM + row)) * NB + n;
                size_t o1 = o0 + (size_t)8 * NB;
                float2 v0 = *(const float2*)(VB + o0);
                float2 v1 = *(const float2*)(VB + o1);
                *(float2*)(O + o0) = make_float2(gam + acc[mt][j][0] + v0.x,
                                                 gam + acc[mt][j][1] + v0.y);
                *(float2*)(O + o1) = make_float2(gam + acc[mt][j][2] + v1.x,
                                                 gam + acc[mt][j][3] + v1.y);
            }
        }
}

// ============================================================================
extern "C" void kernel_launch(void* const* d_in, const int* in_sizes, int n_in,
                              void* d_out, int out_size)
{
    const float* query_a = (const float*)d_in[0];
    const float* value_a = (const float*)d_in[1];
    const float* key_b   = (const float*)d_in[2];
    const float* value_b = (const float*)d_in[3];
    const float* gamma   = (const float*)d_in[4];
    float* out = (float*)d_out;

    cudaFuncSetAttribute(xattn_k1, cudaFuncAttributeMaxDynamicSharedMemorySize, K1_SMEM);
    cudaFuncSetAttribute(xattn_k2, cudaFuncAttributeMaxDynamicSharedMemorySize, K2_SMEM);

    xattn_k1<<<dim3(2, BATCH), 224, K1_SMEM>>>(query_a, key_b);
    xattn_k2<<<dim3(8, BATCH), 256, K2_SMEM>>>(value_a, value_b, gamma, out);
}